// round 1
// baseline (speedup 1.0000x reference)
#include <cuda_runtime.h>
#include <cstdint>
#include <cstddef>

#define DEV __device__ __forceinline__

// ---------------- scratch (static device allocations: allowed) ----------------
__device__ float g_W0[1024u * 4096u];   // 16 MB, tf32-rounded
__device__ float g_W1[4096u * 1024u];   // 16 MB, tf32-rounded
__device__ float g_Xr[8192u * 1024u];   // 32 MB, tf32-rounded copy of x
__device__ float g_H [8192u * 4096u];   // 128 MB, tf32-rounded gelu(h)

// ---------------- helpers ----------------
DEV float rna_tf32(float x) {
    float y;
    asm("cvt.rna.tf32.f32 %0, %1;" : "=f"(y) : "f"(x));
    return y;
}

DEV uint32_t smem_u32(const void* p) {
    return (uint32_t)__cvta_generic_to_shared(p);
}

DEV void cp_async16(uint32_t dst, const void* src) {
    asm volatile("cp.async.cg.shared.global [%0], [%1], 16;\n" :: "r"(dst), "l"(src));
}
DEV void cp_commit() { asm volatile("cp.async.commit_group;\n" ::: "memory"); }
template <int W> DEV void cp_wait() {
    asm volatile("cp.async.wait_group %0;\n" :: "n"(W) : "memory");
}

DEV void mma_tf32(float* c, const uint32_t* a, const uint32_t* b) {
    asm volatile(
        "mma.sync.aligned.m16n8k8.row.col.f32.tf32.tf32.f32 "
        "{%0,%1,%2,%3}, {%4,%5,%6,%7}, {%8,%9}, {%0,%1,%2,%3};\n"
        : "+f"(c[0]), "+f"(c[1]), "+f"(c[2]), "+f"(c[3])
        : "r"(a[0]), "r"(a[1]), "r"(a[2]), "r"(a[3]), "r"(b[0]), "r"(b[1]));
}

DEV float gelu_exact(float x) {          // x * Phi(x) == 0.5*x*(1+erf(x/sqrt(2)))
    return x * normcdff(x);
}

// ---------------- prologue kernels ----------------
__global__ void k_round_x(const float4* __restrict__ x, float4* __restrict__ xr, int n4) {
    int idx = blockIdx.x * blockDim.x + threadIdx.x;
    if (idx < n4) {
        float4 v = x[idx];
        v.x = rna_tf32(v.x); v.y = rna_tf32(v.y);
        v.z = rna_tf32(v.z); v.w = rna_tf32(v.w);
        xr[idx] = v;
    }
}

// W0[(i,j,k)][(o,p,q)] = sum_{r,s} c0a[i,o,r] * c0b[r,j,p,s] * c0c[s,k,q]
// in (8,16,8), out (16,16,16); one block per input row n, 256 threads = (o,p)
__global__ void k_build_w0(const float* __restrict__ c0a,
                           const float* __restrict__ c0b,
                           const float* __restrict__ c0c) {
    __shared__ float a_sh[128];    // c0a[i,:,:]   (o<16, r<8)
    __shared__ float b_sh[1024];   // c0b[:,j,:,:] (r<8, p<16, s<8)
    __shared__ float c_sh[128];    // c0c[:,k,:]   (s<8, q<16) stored [s*16+q]
    const int n = blockIdx.x;
    const int i = n >> 7, j = (n >> 3) & 15, k = n & 7;
    const int t = threadIdx.x;

    if (t < 128) {
        a_sh[t] = c0a[i * 128 + t];
        int s = t >> 4, q = t & 15;
        c_sh[t] = c0c[(s * 8 + k) * 16 + q];
    }
    for (int idx = t; idx < 1024; idx += 256) {
        int r = idx >> 7, p = (idx >> 3) & 15, s = idx & 7;
        b_sh[idx] = c0b[((r * 16 + j) * 16 + p) * 8 + s];
    }
    __syncthreads();

    const int o = t >> 4, p = t & 15;
    float acc[16];
#pragma unroll
    for (int q = 0; q < 16; q++) acc[q] = 0.f;
#pragma unroll
    for (int r = 0; r < 8; r++) {
        float av = a_sh[o * 8 + r];
#pragma unroll
        for (int s = 0; s < 8; s++) {
            float ab = av * b_sh[(r * 16 + p) * 8 + s];
#pragma unroll
            for (int q = 0; q < 16; q++) acc[q] = fmaf(ab, c_sh[s * 16 + q], acc[q]);
        }
    }
    float4* dst = reinterpret_cast<float4*>(&g_W0[(size_t)n * 4096 + (o * 16 + p) * 16]);
#pragma unroll
    for (int qq = 0; qq < 4; qq++)
        dst[qq] = make_float4(rna_tf32(acc[qq * 4 + 0]), rna_tf32(acc[qq * 4 + 1]),
                              rna_tf32(acc[qq * 4 + 2]), rna_tf32(acc[qq * 4 + 3]));
}

// W1: in (16,16,16), out (8,16,8); one block per input row n (4096 blocks, 128 thr)
__global__ void k_build_w1(const float* __restrict__ c1a,
                           const float* __restrict__ c1b,
                           const float* __restrict__ c1c) {
    __shared__ float a_sh[64];     // c1a[i,:,:]   (o<8, r<8)
    __shared__ float b_sh[1024];   // c1b[:,j,:,:] (r<8, p<16, s<8)
    __shared__ float c_sh[64];     // c1c[:,k,:]   (s<8, q<8) stored [s*8+q]
    const int n = blockIdx.x;
    const int i = n >> 8, j = (n >> 4) & 15, k = n & 15;
    const int t = threadIdx.x;

    if (t < 64) {
        a_sh[t] = c1a[i * 64 + t];
    } else {
        int tt = t - 64;           // 0..63
        int s = tt >> 3, q = tt & 7;
        c_sh[tt] = c1c[(s * 16 + k) * 8 + q];
    }
    for (int idx = t; idx < 1024; idx += 128) {
        int r = idx >> 7, p = (idx >> 3) & 15, s = idx & 7;
        b_sh[idx] = c1b[((r * 16 + j) * 16 + p) * 8 + s];
    }
    __syncthreads();

    const int o = t >> 4, p = t & 15;  // o<8
    float acc[8];
#pragma unroll
    for (int q = 0; q < 8; q++) acc[q] = 0.f;
#pragma unroll
    for (int r = 0; r < 8; r++) {
        float av = a_sh[o * 8 + r];
#pragma unroll
        for (int s = 0; s < 8; s++) {
            float ab = av * b_sh[(r * 16 + p) * 8 + s];
#pragma unroll
            for (int q = 0; q < 8; q++) acc[q] = fmaf(ab, c_sh[s * 8 + q], acc[q]);
        }
    }
    float4* dst = reinterpret_cast<float4*>(&g_W1[(size_t)n * 1024 + (o * 16 + p) * 8]);
    dst[0] = make_float4(rna_tf32(acc[0]), rna_tf32(acc[1]), rna_tf32(acc[2]), rna_tf32(acc[3]));
    dst[1] = make_float4(rna_tf32(acc[4]), rna_tf32(acc[5]), rna_tf32(acc[6]), rna_tf32(acc[7]));
}

// ---------------- tf32 GEMM: C = act(A @ B + bias) ----------------
// A: MxK row-major (tf32-prerounded fp32), B: KxN row-major (tf32-prerounded)
// BM=128, BN=128, BK=16, 256 threads, 8 warps in 2(M) x 4(N); warp tile 64x32.
template <bool FUSE_GELU>
__global__ void __launch_bounds__(256, 2)
k_gemm_tf32(const float* __restrict__ A, const float* __restrict__ Bm,
            const float* __restrict__ bias, float* __restrict__ C,
            int M, int N, int K) {
    constexpr int BM = 128, BN = 128, BK = 16;
    constexpr int ASTR = 20;    // BK + 4 pad -> conflict-free A-frag LDS
    constexpr int BSTR = 136;   // BN + 8 pad -> conflict-free B-frag LDS
    __shared__ float As[2][BM * ASTR];
    __shared__ float Bs[2][BK * BSTR];

    const int tid = threadIdx.x;
    const int m0 = blockIdx.y * BM;
    const int n0 = blockIdx.x * BN;
    const int lane = tid & 31;
    const int warp = tid >> 5;
    const int g = lane >> 2, tig = lane & 3;
    const int wm = (warp & 1) * 64;
    const int wn = (warp >> 1) * 32;

    // cp.async copy mapping
    const int am = tid >> 2;            // 0..63 (A rows, +64 for 2nd chunk)
    const int ak = (tid & 3) * 4;       // 0,4,8,12
    const int bk = tid >> 5;            // 0..7  (B rows, +8 for 2nd chunk)
    const int bn = (tid & 31) * 4;      // 0..124

    const float* aptr0 = A + (size_t)(m0 + am) * K + ak;
    const float* aptr1 = A + (size_t)(m0 + am + 64) * K + ak;
    const float* bptr0 = Bm + (size_t)bk * N + n0 + bn;
    const float* bptr1 = Bm + (size_t)(bk + 8) * N + n0 + bn;

    const uint32_t asd0 = smem_u32(&As[0][am * ASTR + ak]);
    const uint32_t asd1 = smem_u32(&As[0][(am + 64) * ASTR + ak]);
    const uint32_t bsd0 = smem_u32(&Bs[0][bk * BSTR + bn]);
    const uint32_t bsd1 = smem_u32(&Bs[0][(bk + 8) * BSTR + bn]);
    const uint32_t aStage = sizeof(float) * BM * ASTR;
    const uint32_t bStage = sizeof(float) * BK * BSTR;

    const int T = K / BK;

    auto issue = [&](int t) {
        const uint32_t st = (uint32_t)(t & 1);
        const size_t koff = (size_t)t * BK;
        cp_async16(asd0 + st * aStage, aptr0 + koff);
        cp_async16(asd1 + st * aStage, aptr1 + koff);
        cp_async16(bsd0 + st * bStage, bptr0 + koff * N);
        cp_async16(bsd1 + st * bStage, bptr1 + koff * N);
        cp_commit();
    };

    float acc[4][4][4];
#pragma unroll
    for (int mi = 0; mi < 4; mi++)
#pragma unroll
        for (int ni = 0; ni < 4; ni++)
#pragma unroll
            for (int q = 0; q < 4; q++) acc[mi][ni][q] = 0.f;

    issue(0);

    for (int t = 0; t < T; ++t) {
        if (t + 1 < T) { issue(t + 1); cp_wait<1>(); }
        else           { cp_wait<0>(); }
        __syncthreads();

        const float* as = As[t & 1];
        const float* bs = Bs[t & 1];
#pragma unroll
        for (int k0 = 0; k0 < BK; k0 += 8) {
            uint32_t af[4][4];
#pragma unroll
            for (int mi = 0; mi < 4; ++mi) {
                const int mb = wm + mi * 16 + g;
                af[mi][0] = __float_as_uint(as[(mb)     * ASTR + k0 + tig]);
                af[mi][1] = __float_as_uint(as[(mb + 8) * ASTR + k0 + tig]);
                af[mi][2] = __float_as_uint(as[(mb)     * ASTR + k0 + tig + 4]);
                af[mi][3] = __float_as_uint(as[(mb + 8) * ASTR + k0 + tig + 4]);
            }
            uint32_t bf[4][2];
#pragma unroll
            for (int ni = 0; ni < 4; ++ni) {
                const int nb = wn + ni * 8 + g;
                bf[ni][0] = __float_as_uint(bs[(k0 + tig)     * BSTR + nb]);
                bf[ni][1] = __float_as_uint(bs[(k0 + tig + 4) * BSTR + nb]);
            }
#pragma unroll
            for (int mi = 0; mi < 4; ++mi)
#pragma unroll
                for (int ni = 0; ni < 4; ++ni)
                    mma_tf32(acc[mi][ni], af[mi], bf[ni]);
        }
        __syncthreads();
    }

    // epilogue
#pragma unroll
    for (int mi = 0; mi < 4; ++mi) {
        const int r0 = m0 + wm + mi * 16 + g;
#pragma unroll
        for (int ni = 0; ni < 4; ++ni) {
            const int col = n0 + wn + ni * 8 + tig * 2;
            const float bv0 = bias[col], bv1 = bias[col + 1];
            float v00 = acc[mi][ni][0] + bv0;
            float v01 = acc[mi][ni][1] + bv1;
            float v10 = acc[mi][ni][2] + bv0;
            float v11 = acc[mi][ni][3] + bv1;
            if (FUSE_GELU) {
                v00 = rna_tf32(gelu_exact(v00));
                v01 = rna_tf32(gelu_exact(v01));
                v10 = rna_tf32(gelu_exact(v10));
                v11 = rna_tf32(gelu_exact(v11));
            }
            *reinterpret_cast<float2*>(&C[(size_t)r0 * N + col])       = make_float2(v00, v01);
            *reinterpret_cast<float2*>(&C[(size_t)(r0 + 8) * N + col]) = make_float2(v10, v11);
        }
    }
}

// ---------------- launch ----------------
extern "C" void kernel_launch(void* const* d_in, const int* in_sizes, int n_in,
                              void* d_out, int out_size) {
    const float* x   = (const float*)d_in[0];
    const float* c0a = (const float*)d_in[1];
    const float* c0b = (const float*)d_in[2];
    const float* c0c = (const float*)d_in[3];
    const float* b0  = (const float*)d_in[4];
    const float* c1a = (const float*)d_in[5];
    const float* c1b = (const float*)d_in[6];
    const float* c1c = (const float*)d_in[7];
    const float* b1  = (const float*)d_in[8];
    float* out = (float*)d_out;

    void *pW0, *pW1, *pXr, *pH;
    cudaGetSymbolAddress(&pW0, g_W0);
    cudaGetSymbolAddress(&pW1, g_W1);
    cudaGetSymbolAddress(&pXr, g_Xr);
    cudaGetSymbolAddress(&pH,  g_H);
    float* W0 = (float*)pW0;
    float* W1 = (float*)pW1;
    float* Xr = (float*)pXr;
    float* H  = (float*)pH;

    // 1) tf32-round x (8192*1024 floats = 2M float4)
    k_round_x<<<2048, 1024>>>((const float4*)x, (float4*)Xr, 8192 * 1024 / 4);
    // 2) materialize TT weight matrices (tf32-rounded)
    k_build_w0<<<1024, 256>>>(c0a, c0b, c0c);
    k_build_w1<<<4096, 128>>>(c1a, c1b, c1c);
    // 3) H = tf32(gelu(Xr @ W0 + b0))   [8192 x 4096]
    k_gemm_tf32<true><<<dim3(4096 / 128, 8192 / 128), 256>>>(Xr, W0, b0, H, 8192, 4096, 1024);
    // 4) out = H @ W1 + b1              [8192 x 1024]
    k_gemm_tf32<false><<<dim3(1024 / 128, 8192 / 128), 256>>>(H, W1, b1, out, 8192, 1024, 4096);
}

// round 4
// speedup vs baseline: 1.0851x; 1.0851x over previous
#include <cuda_runtime.h>
#include <cstdint>
#include <cstddef>

#define DEV __device__ __forceinline__

// ---------------- scratch (static device allocations: allowed) ----------------
__device__ float g_W0[1024u * 4096u];   // 16 MB, W0 [in=1024][out=4096], tf32-rounded
__device__ float g_W1[4096u * 1024u];   // 16 MB, W1 [in=4096][out=1024], tf32-rounded
__device__ float g_Xr[8192u * 1024u];   // 32 MB, tf32-rounded x
__device__ float g_H [8192u * 4096u];   // 128 MB, tf32-rounded gelu(h)

// ---------------- helpers ----------------
DEV float rna_tf32(float x) {
    float y;
    asm("cvt.rna.tf32.f32 %0, %1;" : "=f"(y) : "f"(x));
    return y;
}
DEV uint32_t smem_u32(const void* p) { return (uint32_t)__cvta_generic_to_shared(p); }
DEV void cp_async16(uint32_t dst, const void* src) {
    asm volatile("cp.async.cg.shared.global [%0], [%1], 16;\n" :: "r"(dst), "l"(src));
}
DEV void cp_commit() { asm volatile("cp.async.commit_group;\n" ::: "memory"); }
template <int W> DEV void cp_wait() {
    asm volatile("cp.async.wait_group %0;\n" :: "n"(W) : "memory");
}
DEV void mma_tf32(float* c, const uint32_t* a, const uint32_t* b) {
    asm volatile(
        "mma.sync.aligned.m16n8k8.row.col.f32.tf32.tf32.f32 "
        "{%0,%1,%2,%3}, {%4,%5,%6,%7}, {%8,%9}, {%0,%1,%2,%3};\n"
        : "+f"(c[0]), "+f"(c[1]), "+f"(c[2]), "+f"(c[3])
        : "r"(a[0]), "r"(a[1]), "r"(a[2]), "r"(a[3]), "r"(b[0]), "r"(b[1]));
}
DEV float gelu_exact(float x) { return x * normcdff(x); }

// ---------------- prologue kernels (unchanged from Round 1, known-correct) ----
__global__ void k_round_x(const float4* __restrict__ x, float4* __restrict__ xr, int n4) {
    int idx = blockIdx.x * blockDim.x + threadIdx.x;
    if (idx < n4) {
        float4 v = x[idx];
        v.x = rna_tf32(v.x); v.y = rna_tf32(v.y);
        v.z = rna_tf32(v.z); v.w = rna_tf32(v.w);
        xr[idx] = v;
    }
}

__global__ void k_build_w0(const float* __restrict__ c0a,
                           const float* __restrict__ c0b,
                           const float* __restrict__ c0c) {
    __shared__ float a_sh[128];    // c0a[i,:,:]   (o<16, r<8)
    __shared__ float b_sh[1024];   // c0b[:,j,:,:] (r<8, p<16, s<8)
    __shared__ float c_sh[128];    // c0c[:,k,:]   (s<8, q<16) stored [s*16+q]
    const int n = blockIdx.x;
    const int i = n >> 7, j = (n >> 3) & 15, k = n & 7;
    const int t = threadIdx.x;

    if (t < 128) {
        a_sh[t] = c0a[i * 128 + t];
        int s = t >> 4, q = t & 15;
        c_sh[t] = c0c[(s * 8 + k) * 16 + q];
    }
    for (int idx = t; idx < 1024; idx += 256) {
        int r = idx >> 7, p = (idx >> 3) & 15, s = idx & 7;
        b_sh[idx] = c0b[((r * 16 + j) * 16 + p) * 8 + s];
    }
    __syncthreads();

    const int o = t >> 4, p = t & 15;
    float acc[16];
#pragma unroll
    for (int q = 0; q < 16; q++) acc[q] = 0.f;
#pragma unroll
    for (int r = 0; r < 8; r++) {
        float av = a_sh[o * 8 + r];
#pragma unroll
        for (int s = 0; s < 8; s++) {
            float ab = av * b_sh[(r * 16 + p) * 8 + s];
#pragma unroll
            for (int q = 0; q < 16; q++) acc[q] = fmaf(ab, c_sh[s * 16 + q], acc[q]);
        }
    }
    float4* dst = reinterpret_cast<float4*>(&g_W0[(size_t)n * 4096 + (o * 16 + p) * 16]);
#pragma unroll
    for (int qq = 0; qq < 4; qq++)
        dst[qq] = make_float4(rna_tf32(acc[qq * 4 + 0]), rna_tf32(acc[qq * 4 + 1]),
                              rna_tf32(acc[qq * 4 + 2]), rna_tf32(acc[qq * 4 + 3]));
}

__global__ void k_build_w1(const float* __restrict__ c1a,
                           const float* __restrict__ c1b,
                           const float* __restrict__ c1c) {
    __shared__ float a_sh[64];     // c1a[i,:,:]   (o<8, r<8)
    __shared__ float b_sh[1024];   // c1b[:,j,:,:] (r<8, p<16, s<8)
    __shared__ float c_sh[64];     // c1c[:,k,:]   (s<8, q<8) stored [s*8+q]
    const int n = blockIdx.x;
    const int i = n >> 8, j = (n >> 4) & 15, k = n & 15;
    const int t = threadIdx.x;

    if (t < 64) {
        a_sh[t] = c1a[i * 64 + t];
    } else {
        int tt = t - 64;
        int s = tt >> 3, q = tt & 7;
        c_sh[tt] = c1c[(s * 16 + k) * 8 + q];
    }
    for (int idx = t; idx < 1024; idx += 128) {
        int r = idx >> 7, p = (idx >> 3) & 15, s = idx & 7;
        b_sh[idx] = c1b[((r * 16 + j) * 16 + p) * 8 + s];
    }
    __syncthreads();

    const int o = t >> 4, p = t & 15;  // o<8
    float acc[8];
#pragma unroll
    for (int q = 0; q < 8; q++) acc[q] = 0.f;
#pragma unroll
    for (int r = 0; r < 8; r++) {
        float av = a_sh[o * 8 + r];
#pragma unroll
        for (int s = 0; s < 8; s++) {
            float ab = av * b_sh[(r * 16 + p) * 8 + s];
#pragma unroll
            for (int q = 0; q < 8; q++) acc[q] = fmaf(ab, c_sh[s * 8 + q], acc[q]);
        }
    }
    float4* dst = reinterpret_cast<float4*>(&g_W1[(size_t)n * 1024 + (o * 16 + p) * 8]);
    dst[0] = make_float4(rna_tf32(acc[0]), rna_tf32(acc[1]), rna_tf32(acc[2]), rna_tf32(acc[3]));
    dst[1] = make_float4(rna_tf32(acc[4]), rna_tf32(acc[5]), rna_tf32(acc[6]), rna_tf32(acc[7]));
}

// ---------------- tf32 GEMM: C = act(A @ B + bias) ----------------
// A: MxK row-major (tf32 fp32), B: KxN row-major (tf32 fp32)
// BM=128, BN=128, BK=32, 3-stage cp.async ring, one __syncthreads per stage.
// 256 threads, 8 warps in 2(M) x 4(N); warp tile 64x32.
constexpr int BM = 128, BN = 128, BK = 32, STAGES = 3;
constexpr int ASTR = 36;                       // BK + 4 pad (bank-conflict-free)
constexpr int BSTR = 136;                      // BN + 8 pad
constexpr int A_FLOATS = BM * ASTR;            // 4608
constexpr int B_FLOATS = BK * BSTR;            // 4352
constexpr int STAGE_FLOATS = A_FLOATS + B_FLOATS;     // 8960
constexpr int GEMM_SMEM = STAGES * STAGE_FLOATS * 4;  // 107520 B

template <bool FUSE_GELU>
__global__ void __launch_bounds__(256, 2)
k_gemm_tf32(const float* __restrict__ A, const float* __restrict__ Bm,
            const float* __restrict__ bias, float* __restrict__ C,
            int M, int N, int K) {
    extern __shared__ float smem_f[];
    const uint32_t sbase = smem_u32(smem_f);

    const int tid = threadIdx.x;
    const int m0 = blockIdx.y * BM;
    const int n0 = blockIdx.x * BN;
    const int lane = tid & 31;
    const int warp = tid >> 5;
    const int g = lane >> 2, tig = lane & 3;
    const int wm = (warp & 1) * 64;
    const int wn = (warp >> 1) * 32;

    const int T = K / BK;

    // copy mappings (4 x 16B chunks per thread for A, 4 for B)
    const int arow = tid >> 3;          // +32 per chunk index
    const int akc  = (tid & 7) * 4;
    const int brow = tid >> 5;          // +8 per chunk index
    const int bnc  = (tid & 31) * 4;

    const float* agl = A + (size_t)(m0 + arow) * K + akc;
    const float* bgl = Bm + (size_t)brow * N + n0 + bnc;

    auto issue = [&](int t) {
        const int st = t % STAGES;
        const uint32_t sa = sbase + (uint32_t)(st * STAGE_FLOATS) * 4u;
        const uint32_t sb2 = sa + A_FLOATS * 4u;
        const size_t akoff = (size_t)t * BK;
#pragma unroll
        for (int i = 0; i < 4; i++)
            cp_async16(sa + (uint32_t)((arow + 32 * i) * ASTR + akc) * 4u,
                       agl + (size_t)(32 * i) * K + akoff);
#pragma unroll
        for (int i = 0; i < 4; i++)
            cp_async16(sb2 + (uint32_t)((brow + 8 * i) * BSTR + bnc) * 4u,
                       bgl + (akoff + (size_t)(8 * i)) * N);
        cp_commit();
    };

    float acc[4][4][4];
#pragma unroll
    for (int mi = 0; mi < 4; mi++)
#pragma unroll
        for (int ni = 0; ni < 4; ni++)
#pragma unroll
            for (int q = 0; q < 4; q++) acc[mi][ni][q] = 0.f;

    issue(0);
    issue(1);

    for (int t = 0; t < T; ++t) {
        cp_wait<1>();            // my stage-t chunks have landed
        __syncthreads();         // everyone's landed; everyone done with buffer (t+2)%3
        if (t + 2 < T) issue(t + 2);

        const float* as = smem_f + (t % STAGES) * STAGE_FLOATS;
        const float* bs = as + A_FLOATS;
#pragma unroll
        for (int k0 = 0; k0 < BK; k0 += 8) {
            uint32_t af[4][4];
#pragma unroll
            for (int mi = 0; mi < 4; ++mi) {
                const int mb = wm + mi * 16 + g;
                af[mi][0] = __float_as_uint(as[(mb)     * ASTR + k0 + tig]);
                af[mi][1] = __float_as_uint(as[(mb + 8) * ASTR + k0 + tig]);
                af[mi][2] = __float_as_uint(as[(mb)     * ASTR + k0 + tig + 4]);
                af[mi][3] = __float_as_uint(as[(mb + 8) * ASTR + k0 + tig + 4]);
            }
            uint32_t bf[4][2];
#pragma unroll
            for (int ni = 0; ni < 4; ++ni) {
                const int nb = wn + ni * 8 + g;
                bf[ni][0] = __float_as_uint(bs[(k0 + tig)     * BSTR + nb]);
                bf[ni][1] = __float_as_uint(bs[(k0 + tig + 4) * BSTR + nb]);
            }
#pragma unroll
            for (int mi = 0; mi < 4; ++mi)
#pragma unroll
                for (int ni = 0; ni < 4; ++ni)
                    mma_tf32(acc[mi][ni], af[mi], bf[ni]);
        }
        __syncthreads();         // done reading buffer t%3 before it is refilled at t+1... (issue order guarded by top sync)
    }

    // epilogue
#pragma unroll
    for (int mi = 0; mi < 4; ++mi) {
        const int r0 = m0 + wm + mi * 16 + g;
#pragma unroll
        for (int ni = 0; ni < 4; ++ni) {
            const int col = n0 + wn + ni * 8 + tig * 2;
            const float bv0 = bias[col], bv1 = bias[col + 1];
            float v00 = acc[mi][ni][0] + bv0;
            float v01 = acc[mi][ni][1] + bv1;
            float v10 = acc[mi][ni][2] + bv0;
            float v11 = acc[mi][ni][3] + bv1;
            if (FUSE_GELU) {
                v00 = rna_tf32(gelu_exact(v00));
                v01 = rna_tf32(gelu_exact(v01));
                v10 = rna_tf32(gelu_exact(v10));
                v11 = rna_tf32(gelu_exact(v11));
            }
            *reinterpret_cast<float2*>(&C[(size_t)r0 * N + col])       = make_float2(v00, v01);
            *reinterpret_cast<float2*>(&C[(size_t)(r0 + 8) * N + col]) = make_float2(v10, v11);
        }
    }
}

// ---------------- launch ----------------
extern "C" void kernel_launch(void* const* d_in, const int* in_sizes, int n_in,
                              void* d_out, int out_size) {
    const float* x   = (const float*)d_in[0];
    const float* c0a = (const float*)d_in[1];
    const float* c0b = (const float*)d_in[2];
    const float* c0c = (const float*)d_in[3];
    const float* b0  = (const float*)d_in[4];
    const float* c1a = (const float*)d_in[5];
    const float* c1b = (const float*)d_in[6];
    const float* c1c = (const float*)d_in[7];
    const float* b1  = (const float*)d_in[8];
    float* out = (float*)d_out;

    void *pW0, *pW1, *pXr, *pH;
    cudaGetSymbolAddress(&pW0, g_W0);
    cudaGetSymbolAddress(&pW1, g_W1);
    cudaGetSymbolAddress(&pXr, g_Xr);
    cudaGetSymbolAddress(&pH,  g_H);
    float* W0 = (float*)pW0;
    float* W1 = (float*)pW1;
    float* Xr = (float*)pXr;
    float* H  = (float*)pH;

    cudaFuncSetAttribute(k_gemm_tf32<true>,  cudaFuncAttributeMaxDynamicSharedMemorySize, GEMM_SMEM);
    cudaFuncSetAttribute(k_gemm_tf32<false>, cudaFuncAttributeMaxDynamicSharedMemorySize, GEMM_SMEM);

    // 1) tf32-round x
    k_round_x<<<2048, 1024>>>((const float4*)x, (float4*)Xr, 8192 * 1024 / 4);
    // 2) materialize TT weight matrices (tf32-rounded)
    k_build_w0<<<1024, 256>>>(c0a, c0b, c0c);
    k_build_w1<<<4096, 128>>>(c1a, c1b, c1c);
    // 3) H = tf32(gelu(Xr @ W0 + b0))   [8192 x 4096]
    k_gemm_tf32<true><<<dim3(4096 / BN, 8192 / BM), 256, GEMM_SMEM>>>(Xr, W0, b0, H, 8192, 4096, 1024);
    // 4) out = H @ W1 + b1              [8192 x 1024]
    k_gemm_tf32<false><<<dim3(1024 / BN, 8192 / BM), 256, GEMM_SMEM>>>(H, W1, b1, out, 8192, 1024, 4096);
}

// round 5
// speedup vs baseline: 1.3587x; 1.2521x over previous
#include <cuda_runtime.h>
#include <cuda_fp16.h>
#include <cstdint>
#include <cstddef>

#define DEV __device__ __forceinline__

// ---------------- scratch (static device allocations: allowed) ----------------
__device__ __half g_W0h[4096u * 1024u];  // 8 MB, W0^T [out=4096][in=1024] fp16
__device__ __half g_W1h[1024u * 4096u];  // 8 MB, W1^T [out=1024][in=4096] fp16
__device__ __half g_Xh [8192u * 1024u];  // 16 MB, fp16 x
__device__ __half g_Hh [8192u * 4096u];  // 64 MB, fp16 gelu(h)

// ---------------- helpers ----------------
DEV uint32_t smem_u32(const void* p) { return (uint32_t)__cvta_generic_to_shared(p); }
DEV void cp_async16(uint32_t dst, const void* src) {
    asm volatile("cp.async.cg.shared.global [%0], [%1], 16;\n" :: "r"(dst), "l"(src));
}
DEV void cp_commit() { asm volatile("cp.async.commit_group;\n" ::: "memory"); }
template <int W> DEV void cp_wait() {
    asm volatile("cp.async.wait_group %0;\n" :: "n"(W) : "memory");
}
DEV void mma_f16(float* c, const uint32_t* a, const uint32_t* b) {
    asm volatile(
        "mma.sync.aligned.m16n8k16.row.col.f32.f16.f16.f32 "
        "{%0,%1,%2,%3}, {%4,%5,%6,%7}, {%8,%9}, {%0,%1,%2,%3};\n"
        : "+f"(c[0]), "+f"(c[1]), "+f"(c[2]), "+f"(c[3])
        : "r"(a[0]), "r"(a[1]), "r"(a[2]), "r"(a[3]), "r"(b[0]), "r"(b[1]));
}
DEV float gelu_exact(float x) { return x * normcdff(x); }

// ---------------- prologue: x (fp32) -> fp16 ----------------
__global__ void k_x_to_h(const float4* __restrict__ x, __half2* __restrict__ xh, int n4) {
    int idx = blockIdx.x * blockDim.x + threadIdx.x;
    if (idx < n4) {
        float4 v = x[idx];
        xh[2 * idx]     = __floats2half2_rn(v.x, v.y);
        xh[2 * idx + 1] = __floats2half2_rn(v.z, v.w);
    }
}

// ---------------- transposed TT weight builders (fp16 out) ----------------
// W0t[m][n] = sum_{r,s} c0a[(i*16+o)*8+r] * c0b[((r*16+j)*16+p)*8+s] * c0c[(s*8+k)*16+q]
//   n=(i*16+j)*8+k (in 8,16,8), m=(o*16+p)*16+q (out 16,16,16). Block per m, 256 thr.
__global__ void k_build_w0t(const float* __restrict__ c0a,
                            const float* __restrict__ c0b,
                            const float* __restrict__ c0c) {
    __shared__ float a_sh[64], c_sh[64], b_sh[1024], bc[1024];
    const int m = blockIdx.x;
    const int o = m >> 8, p = (m >> 4) & 15, q = m & 15;
    const int t = threadIdx.x;

    if (t < 64) {                       // a_sh[i*8+r]
        int i = t >> 3, r = t & 7;
        a_sh[t] = c0a[(i * 16 + o) * 8 + r];
    } else if (t < 128) {               // c_sh[s*8+k]
        int tt = t - 64, s = tt >> 3, k = tt & 7;
        c_sh[tt] = c0c[(s * 8 + k) * 16 + q];
    }
    for (int idx = t; idx < 1024; idx += 256) {   // b_sh[(r*16+j)*8+s]
        int rj = idx >> 3, s = idx & 7;
        b_sh[idx] = c0b[(rj * 16 + p) * 8 + s];
    }
    __syncthreads();
    for (int idx = t; idx < 1024; idx += 256) {   // bc[(r*16+j)*8+k]
        int rj = idx >> 3, k = idx & 7;
        float acc = 0.f;
#pragma unroll
        for (int s = 0; s < 8; s++) acc = fmaf(b_sh[rj * 8 + s], c_sh[s * 8 + k], acc);
        bc[idx] = acc;
    }
    __syncthreads();
    float v[4];
#pragma unroll
    for (int d = 0; d < 4; d++) {
        int n = 4 * t + d;
        int i = n >> 7, j = (n >> 3) & 15, k = n & 7;
        float acc = 0.f;
#pragma unroll
        for (int r = 0; r < 8; r++) acc = fmaf(a_sh[i * 8 + r], bc[(r * 16 + j) * 8 + k], acc);
        v[d] = acc;
    }
    __half2* dst = reinterpret_cast<__half2*>(&g_W0h[(size_t)m * 1024 + 4 * t]);
    dst[0] = __floats2half2_rn(v[0], v[1]);
    dst[1] = __floats2half2_rn(v[2], v[3]);
}

// W1t[m][n]: n=(i*16+j)*16+k (in 16,16,16), m=(o*16+p)*8+q (out 8,16,8)
// c1a[(i*8+o)*8+r], c1b[((r*16+j)*16+p)*8+s], c1c[(s*16+k)*8+q]. Block per m, 256 thr.
__global__ void k_build_w1t(const float* __restrict__ c1a,
                            const float* __restrict__ c1b,
                            const float* __restrict__ c1c) {
    __shared__ float a_sh[128], c_sh[128], b_sh[1024], bc[2048];
    const int m = blockIdx.x;
    const int o = m >> 7, p = (m >> 3) & 15, q = m & 7;
    const int t = threadIdx.x;

    if (t < 128) {                      // a_sh[i*8+r]
        int i = t >> 3, r = t & 7;
        a_sh[t] = c1a[(i * 8 + o) * 8 + r];
    } else {                            // c_sh[s*16+k]
        int tt = t - 128, s = tt >> 4, k = tt & 15;
        c_sh[tt] = c1c[(s * 16 + k) * 8 + q];
    }
    for (int idx = t; idx < 1024; idx += 256) {   // b_sh[(r*16+j)*8+s]
        int rj = idx >> 3, s = idx & 7;
        b_sh[idx] = c1b[(rj * 16 + p) * 8 + s];
    }
    __syncthreads();
    for (int idx = t; idx < 2048; idx += 256) {   // bc[(r*16+j)*16+k]
        int rj = idx >> 4, k = idx & 15;
        float acc = 0.f;
#pragma unroll
        for (int s = 0; s < 8; s++) acc = fmaf(b_sh[rj * 8 + s], c_sh[s * 16 + k], acc);
        bc[idx] = acc;
    }
    __syncthreads();
    const int i = t >> 4, j = t & 15;   // n = 16t + k
    float v[16];
#pragma unroll
    for (int k = 0; k < 16; k++) {
        float acc = 0.f;
#pragma unroll
        for (int r = 0; r < 8; r++) acc = fmaf(a_sh[i * 8 + r], bc[(r * 16 + j) * 16 + k], acc);
        v[k] = acc;
    }
    __half2* dst = reinterpret_cast<__half2*>(&g_W1h[(size_t)m * 4096 + 16 * t]);
#pragma unroll
    for (int d = 0; d < 8; d++)
        dst[d] = __floats2half2_rn(v[2 * d], v[2 * d + 1]);
}

// ---------------- fp16 GEMM: C = act(A @ B^T + bias) ----------------
// A: [M][K] fp16 row-major; B: [N][K] fp16 row-major (weights pre-transposed).
// BM=BN=128, BK=64 halves (32 words), 3-stage cp.async ring, 256 thr (8 warps 2x4).
constexpr int BM = 128, BN = 128, BKH = 64, STAGES = 3;
constexpr int STRW = 36;                               // 32 words + 4 pad
constexpr int A_WORDS = BM * STRW;                     // 4608
constexpr int B_WORDS = BN * STRW;                     // 4608
constexpr int STAGE_WORDS = A_WORDS + B_WORDS;         // 9216
constexpr int GEMM_SMEM = STAGES * STAGE_WORDS * 4;    // 110592 B

template <bool FUSE_GELU, bool HALF_OUT>
__global__ void __launch_bounds__(256, 2)
k_gemm_f16(const __half* __restrict__ A, const __half* __restrict__ Bg,
           const float* __restrict__ bias, void* __restrict__ Cv,
           int M, int N, int K) {
    extern __shared__ uint32_t smem_w[];
    const uint32_t sbase = smem_u32(smem_w);

    const int tid = threadIdx.x;
    const int m0 = blockIdx.y * BM;
    const int n0 = blockIdx.x * BN;
    const int lane = tid & 31;
    const int warp = tid >> 5;
    const int g = lane >> 2, tig = lane & 3;
    const int wm = (warp & 1) * 64;        // warp M offset (2 warps in M)
    const int wn = (warp >> 1) * 32;       // warp N offset (4 warps in N)

    const int T = K / BKH;

    // cp.async mapping: row = tid>>1 (0..127), 4 x 16B chunks per thread per tile
    const int crow = tid >> 1;
    const int cwordbase = (tid & 1) * 16;               // word col base (0 or 16)
    const __half* agl = A + (size_t)(m0 + crow) * K + cwordbase * 2;
    const __half* bgl = Bg + (size_t)(n0 + crow) * K + cwordbase * 2;
    const uint32_t sa_off = (uint32_t)(crow * STRW + cwordbase) * 4u;

    auto issue = [&](int t) {
        const int st = t % STAGES;
        const uint32_t sa = sbase + (uint32_t)(st * STAGE_WORDS) * 4u + sa_off;
        const uint32_t sb = sa + (uint32_t)A_WORDS * 4u;
        const size_t koff = (size_t)t * BKH;
#pragma unroll
        for (int i = 0; i < 4; i++)
            cp_async16(sa + i * 16u, agl + koff + i * 8);
#pragma unroll
        for (int i = 0; i < 4; i++)
            cp_async16(sb + i * 16u, bgl + koff + i * 8);
        cp_commit();
    };

    float acc[4][4][4];
#pragma unroll
    for (int mi = 0; mi < 4; mi++)
#pragma unroll
        for (int ni = 0; ni < 4; ni++)
#pragma unroll
            for (int q = 0; q < 4; q++) acc[mi][ni][q] = 0.f;

    issue(0);
    issue(1);

    for (int t = 0; t < T; ++t) {
        cp_wait<1>();            // stage t landed (t+1 may still be in flight)
        __syncthreads();         // all threads finished reading buffer (t+2)%3
        if (t + 2 < T) issue(t + 2);

        const uint32_t* as = smem_w + (t % STAGES) * STAGE_WORDS;
        const uint32_t* bs = as + A_WORDS;
#pragma unroll
        for (int k16 = 0; k16 < 4; ++k16) {          // 4 x K=16 per stage
            const int k0w = k16 * 8;                 // word offset
            uint32_t af[4][4];
#pragma unroll
            for (int mi = 0; mi < 4; ++mi) {
                const int mb = wm + mi * 16 + g;
                af[mi][0] = as[(mb)     * STRW + k0w + tig];
                af[mi][1] = as[(mb + 8) * STRW + k0w + tig];
                af[mi][2] = as[(mb)     * STRW + k0w + tig + 4];
                af[mi][3] = as[(mb + 8) * STRW + k0w + tig + 4];
            }
            uint32_t bf[4][2];
#pragma unroll
            for (int ni = 0; ni < 4; ++ni) {
                const int nb = wn + ni * 8 + g;
                bf[ni][0] = bs[nb * STRW + k0w + tig];
                bf[ni][1] = bs[nb * STRW + k0w + tig + 4];
            }
#pragma unroll
            for (int mi = 0; mi < 4; ++mi)
#pragma unroll
                for (int ni = 0; ni < 4; ++ni)
                    mma_f16(acc[mi][ni], af[mi], bf[ni]);
        }
    }
    // note: no trailing sync needed; epilogue reads only registers

    // ---- epilogue ----
#pragma unroll
    for (int mi = 0; mi < 4; ++mi) {
        const int r0 = m0 + wm + mi * 16 + g;
#pragma unroll
        for (int ni = 0; ni < 4; ++ni) {
            const int col = n0 + wn + ni * 8 + tig * 2;
            const float bv0 = bias[col], bv1 = bias[col + 1];
            float v00 = acc[mi][ni][0] + bv0;
            float v01 = acc[mi][ni][1] + bv1;
            float v10 = acc[mi][ni][2] + bv0;
            float v11 = acc[mi][ni][3] + bv1;
            if (FUSE_GELU) {
                v00 = gelu_exact(v00);
                v01 = gelu_exact(v01);
                v10 = gelu_exact(v10);
                v11 = gelu_exact(v11);
            }
            if (HALF_OUT) {
                __half* C = (__half*)Cv;
                *reinterpret_cast<__half2*>(&C[(size_t)r0 * N + col]) =
                    __floats2half2_rn(v00, v01);
                *reinterpret_cast<__half2*>(&C[(size_t)(r0 + 8) * N + col]) =
                    __floats2half2_rn(v10, v11);
            } else {
                float* C = (float*)Cv;
                *reinterpret_cast<float2*>(&C[(size_t)r0 * N + col])       = make_float2(v00, v01);
                *reinterpret_cast<float2*>(&C[(size_t)(r0 + 8) * N + col]) = make_float2(v10, v11);
            }
        }
    }
}

// ---------------- launch ----------------
extern "C" void kernel_launch(void* const* d_in, const int* in_sizes, int n_in,
                              void* d_out, int out_size) {
    const float* x   = (const float*)d_in[0];
    const float* c0a = (const float*)d_in[1];
    const float* c0b = (const float*)d_in[2];
    const float* c0c = (const float*)d_in[3];
    const float* b0  = (const float*)d_in[4];
    const float* c1a = (const float*)d_in[5];
    const float* c1b = (const float*)d_in[6];
    const float* c1c = (const float*)d_in[7];
    const float* b1  = (const float*)d_in[8];
    float* out = (float*)d_out;

    void *pW0, *pW1, *pXh, *pHh;
    cudaGetSymbolAddress(&pW0, g_W0h);
    cudaGetSymbolAddress(&pW1, g_W1h);
    cudaGetSymbolAddress(&pXh, g_Xh);
    cudaGetSymbolAddress(&pHh, g_Hh);
    __half* W0h = (__half*)pW0;
    __half* W1h = (__half*)pW1;
    __half* Xh  = (__half*)pXh;
    __half* Hh  = (__half*)pHh;

    cudaFuncSetAttribute(k_gemm_f16<true, true>,
                         cudaFuncAttributeMaxDynamicSharedMemorySize, GEMM_SMEM);
    cudaFuncSetAttribute(k_gemm_f16<false, false>,
                         cudaFuncAttributeMaxDynamicSharedMemorySize, GEMM_SMEM);

    // 1) convert x -> fp16
    k_x_to_h<<<2048, 1024>>>((const float4*)x, (__half2*)Xh, 8192 * 1024 / 4);
    // 2) materialize transposed TT weight matrices (fp16)
    k_build_w0t<<<4096, 256>>>(c0a, c0b, c0c);
    k_build_w1t<<<1024, 256>>>(c1a, c1b, c1c);
    // 3) Hh = fp16(gelu(Xh @ W0h^T + b0))   [8192 x 4096]
    k_gemm_f16<true, true><<<dim3(4096 / BN, 8192 / BM), 256, GEMM_SMEM>>>(
        Xh, W0h, b0, Hh, 8192, 4096, 1024);
    // 4) out = Hh @ W1h^T + b1              [8192 x 1024] fp32
    k_gemm_f16<false, false><<<dim3(1024 / BN, 8192 / BM), 256, GEMM_SMEM>>>(
        Hh, W1h, b1, out, 8192, 1024, 4096);
}

// round 6
// speedup vs baseline: 1.4854x; 1.0933x over previous
#include <cuda_runtime.h>
#include <cuda_fp16.h>
#include <cstdint>
#include <cstddef>

#define DEV __device__ __forceinline__

// ---------------- scratch (static device allocations: allowed) ----------------
__device__ __half g_W0h[4096u * 1024u];  // 8 MB, W0^T [out=4096][in=1024] fp16
__device__ __half g_W1h[1024u * 4096u];  // 8 MB, W1^T [out=1024][in=4096] fp16
__device__ __half g_Xh [8192u * 1024u];  // 16 MB, fp16 x
__device__ __half g_Hh [8192u * 4096u];  // 64 MB, fp16 gelu(h)

// ---------------- helpers ----------------
DEV uint32_t smem_u32(const void* p) { return (uint32_t)__cvta_generic_to_shared(p); }
DEV void cp_async16(uint32_t dst, const void* src) {
    asm volatile("cp.async.cg.shared.global [%0], [%1], 16;\n" :: "r"(dst), "l"(src));
}
DEV void cp_commit() { asm volatile("cp.async.commit_group;\n" ::: "memory"); }
template <int W> DEV void cp_wait() {
    asm volatile("cp.async.wait_group %0;\n" :: "n"(W) : "memory");
}
DEV void mma_f16(float* c, const uint32_t* a, const uint32_t b0, const uint32_t b1) {
    asm volatile(
        "mma.sync.aligned.m16n8k16.row.col.f32.f16.f16.f32 "
        "{%0,%1,%2,%3}, {%4,%5,%6,%7}, {%8,%9}, {%0,%1,%2,%3};\n"
        : "+f"(c[0]), "+f"(c[1]), "+f"(c[2]), "+f"(c[3])
        : "r"(a[0]), "r"(a[1]), "r"(a[2]), "r"(a[3]), "r"(b0), "r"(b1));
}
DEV void ldsm_x4(uint32_t* r, uint32_t addr) {
    asm volatile("ldmatrix.sync.aligned.m8n8.x4.shared.b16 {%0,%1,%2,%3}, [%4];"
                 : "=r"(r[0]), "=r"(r[1]), "=r"(r[2]), "=r"(r[3]) : "r"(addr));
}
DEV float gelu_exact(float x) { return x * normcdff(x); }

// ---------------- prologue: x (fp32) -> fp16 ----------------
__global__ void k_x_to_h(const float4* __restrict__ x, __half2* __restrict__ xh, int n4) {
    int idx = blockIdx.x * blockDim.x + threadIdx.x;
    if (idx < n4) {
        float4 v = x[idx];
        xh[2 * idx]     = __floats2half2_rn(v.x, v.y);
        xh[2 * idx + 1] = __floats2half2_rn(v.z, v.w);
    }
}

// ---------------- transposed TT weight builders (fp16 out) ----------------
__global__ void k_build_w0t(const float* __restrict__ c0a,
                            const float* __restrict__ c0b,
                            const float* __restrict__ c0c) {
    __shared__ float a_sh[64], c_sh[64], b_sh[1024], bc[1024];
    const int m = blockIdx.x;
    const int o = m >> 8, p = (m >> 4) & 15, q = m & 15;
    const int t = threadIdx.x;

    if (t < 64) {                       // a_sh[i*8+r]
        int i = t >> 3, r = t & 7;
        a_sh[t] = c0a[(i * 16 + o) * 8 + r];
    } else if (t < 128) {               // c_sh[s*8+k]
        int tt = t - 64, s = tt >> 3, k = tt & 7;
        c_sh[tt] = c0c[(s * 8 + k) * 16 + q];
    }
    for (int idx = t; idx < 1024; idx += 256) {   // b_sh[(r*16+j)*8+s]
        int rj = idx >> 3, s = idx & 7;
        b_sh[idx] = c0b[(rj * 16 + p) * 8 + s];
    }
    __syncthreads();
    for (int idx = t; idx < 1024; idx += 256) {   // bc[(r*16+j)*8+k]
        int rj = idx >> 3, k = idx & 7;
        float acc = 0.f;
#pragma unroll
        for (int s = 0; s < 8; s++) acc = fmaf(b_sh[rj * 8 + s], c_sh[s * 8 + k], acc);
        bc[idx] = acc;
    }
    __syncthreads();
    float v[4];
#pragma unroll
    for (int d = 0; d < 4; d++) {
        int n = 4 * t + d;
        int i = n >> 7, j = (n >> 3) & 15, k = n & 7;
        float acc = 0.f;
#pragma unroll
        for (int r = 0; r < 8; r++) acc = fmaf(a_sh[i * 8 + r], bc[(r * 16 + j) * 8 + k], acc);
        v[d] = acc;
    }
    __half2* dst = reinterpret_cast<__half2*>(&g_W0h[(size_t)m * 1024 + 4 * t]);
    dst[0] = __floats2half2_rn(v[0], v[1]);
    dst[1] = __floats2half2_rn(v[2], v[3]);
}

__global__ void k_build_w1t(const float* __restrict__ c1a,
                            const float* __restrict__ c1b,
                            const float* __restrict__ c1c) {
    __shared__ float a_sh[128], c_sh[128], b_sh[1024], bc[2048];
    const int m = blockIdx.x;
    const int o = m >> 7, p = (m >> 3) & 15, q = m & 7;
    const int t = threadIdx.x;

    if (t < 128) {                      // a_sh[i*8+r]
        int i = t >> 3, r = t & 7;
        a_sh[t] = c1a[(i * 8 + o) * 8 + r];
    } else {                            // c_sh[s*16+k]
        int tt = t - 128, s = tt >> 4, k = tt & 15;
        c_sh[tt] = c1c[(s * 16 + k) * 8 + q];
    }
    for (int idx = t; idx < 1024; idx += 256) {   // b_sh[(r*16+j)*8+s]
        int rj = idx >> 3, s = idx & 7;
        b_sh[idx] = c1b[(rj * 16 + p) * 8 + s];
    }
    __syncthreads();
    for (int idx = t; idx < 2048; idx += 256) {   // bc[(r*16+j)*16+k]
        int rj = idx >> 4, k = idx & 15;
        float acc = 0.f;
#pragma unroll
        for (int s = 0; s < 8; s++) acc = fmaf(b_sh[rj * 8 + s], c_sh[s * 16 + k], acc);
        bc[idx] = acc;
    }
    __syncthreads();
    const int i = t >> 4, j = t & 15;   // n = 16t + k
    float v[16];
#pragma unroll
    for (int k = 0; k < 16; k++) {
        float acc = 0.f;
#pragma unroll
        for (int r = 0; r < 8; r++) acc = fmaf(a_sh[i * 8 + r], bc[(r * 16 + j) * 16 + k], acc);
        v[k] = acc;
    }
    __half2* dst = reinterpret_cast<__half2*>(&g_W1h[(size_t)m * 4096 + 16 * t]);
#pragma unroll
    for (int d = 0; d < 8; d++)
        dst[d] = __floats2half2_rn(v[2 * d], v[2 * d + 1]);
}

// ---------------- fp16 GEMM: C = act(A @ B^T + bias) ----------------
// A: [M][K] fp16 row-major; B: [N][K] fp16 row-major (weights pre-transposed).
// BM=BN=128, BK=64 halves, 3-stage cp.async ring, ldmatrix.x4 fragment feed.
constexpr int BM = 128, BN = 128, BKH = 64, STAGES = 3;
constexpr int STRW = 36;                               // 32 words + 4 pad
constexpr int ROWB = STRW * 4;                         // 144 B row stride
constexpr int A_WORDS = BM * STRW;                     // 4608
constexpr int B_WORDS = BN * STRW;                     // 4608
constexpr int STAGE_WORDS = A_WORDS + B_WORDS;         // 9216
constexpr int STAGE_BYTES = STAGE_WORDS * 4;
constexpr int GEMM_SMEM = STAGES * STAGE_BYTES;        // 110592 B

template <bool FUSE_GELU, bool HALF_OUT>
__global__ void __launch_bounds__(256, 2)
k_gemm_f16(const __half* __restrict__ A, const __half* __restrict__ Bg,
           const float* __restrict__ bias, void* __restrict__ Cv,
           int M, int N, int K) {
    extern __shared__ uint32_t smem_w[];
    const uint32_t sbase = smem_u32(smem_w);

    const int tid = threadIdx.x;
    const int m0 = blockIdx.y * BM;
    const int n0 = blockIdx.x * BN;
    const int lane = tid & 31;
    const int warp = tid >> 5;
    const int g = lane >> 2, tig = lane & 3;
    const int wm = (warp & 1) * 64;        // warp M offset (2 warps in M)
    const int wn = (warp >> 1) * 32;       // warp N offset (4 warps in N)

    const int T = K / BKH;

    // cp.async mapping: row = tid>>1, 4 x 16B chunks per operand per thread
    const int crow = tid >> 1;
    const int cwordbase = (tid & 1) * 16;
    const __half* agl = A + (size_t)(m0 + crow) * K + cwordbase * 2;
    const __half* bgl = Bg + (size_t)(n0 + crow) * K + cwordbase * 2;
    const uint32_t sa_off = (uint32_t)(crow * STRW + cwordbase) * 4u;

    auto issue = [&](int t) {
        const int st = t % STAGES;
        const uint32_t sa = sbase + (uint32_t)(st * STAGE_BYTES) + sa_off;
        const uint32_t sb = sa + (uint32_t)A_WORDS * 4u;
        const size_t koff = (size_t)t * BKH;
#pragma unroll
        for (int i = 0; i < 4; i++)
            cp_async16(sa + i * 16u, agl + koff + i * 8);
#pragma unroll
        for (int i = 0; i < 4; i++)
            cp_async16(sb + i * 16u, bgl + koff + i * 8);
        cp_commit();
    };

    // ldmatrix base addresses (stage 0)
    // A frag (m16k16): th0-15 -> rows mb+(lane&15) @k0; th16-31 -> same rows @k8
    const uint32_t aLdsm = sbase
        + (uint32_t)((wm + (lane & 15)) * ROWB)
        + (uint32_t)((lane >> 4) * 16);
    // B frag pair (two n8k16): th0-7 rows nb..+7 @k0 (b0 of ni), th8-15 same @k8 (b1),
    // th16-23 rows nb+8..15 @k0 (b0 of ni+1), th24-31 same @k8 (b1 of ni+1)
    const uint32_t bLdsm = sbase + (uint32_t)A_WORDS * 4u
        + (uint32_t)((wn + ((lane >> 4) << 3) + (lane & 7)) * ROWB)
        + (uint32_t)(((lane >> 3) & 1) * 16);

    float acc[4][4][4];
#pragma unroll
    for (int mi = 0; mi < 4; mi++)
#pragma unroll
        for (int ni = 0; ni < 4; ni++)
#pragma unroll
            for (int q = 0; q < 4; q++) acc[mi][ni][q] = 0.f;

    issue(0);
    issue(1);

    for (int t = 0; t < T; ++t) {
        cp_wait<1>();            // stage t landed
        __syncthreads();         // everyone done with buffer (t+2)%3
        if (t + 2 < T) issue(t + 2);

        const uint32_t stoff = (uint32_t)((t % STAGES) * STAGE_BYTES);
#pragma unroll
        for (int k16 = 0; k16 < 4; ++k16) {          // 4 x K=16 per stage
            const uint32_t kb = (uint32_t)(k16 * 32); // 8 words = 32 B per k16
            uint32_t af[4][4];
#pragma unroll
            for (int mi = 0; mi < 4; ++mi)
                ldsm_x4(af[mi], aLdsm + stoff + (uint32_t)(mi * 16 * ROWB) + kb);
            uint32_t bq[2][4];
#pragma unroll
            for (int nip = 0; nip < 2; ++nip)
                ldsm_x4(bq[nip], bLdsm + stoff + (uint32_t)(nip * 16 * ROWB) + kb);
#pragma unroll
            for (int mi = 0; mi < 4; ++mi)
#pragma unroll
                for (int ni = 0; ni < 4; ++ni)
                    mma_f16(acc[mi][ni], af[mi], bq[ni >> 1][2 * (ni & 1)],
                            bq[ni >> 1][2 * (ni & 1) + 1]);
        }
    }

    // ---- epilogue ----
#pragma unroll
    for (int mi = 0; mi < 4; ++mi) {
        const int r0 = m0 + wm + mi * 16 + g;
#pragma unroll
        for (int ni = 0; ni < 4; ++ni) {
            const int col = n0 + wn + ni * 8 + tig * 2;
            const float bv0 = bias[col], bv1 = bias[col + 1];
            float v00 = acc[mi][ni][0] + bv0;
            float v01 = acc[mi][ni][1] + bv1;
            float v10 = acc[mi][ni][2] + bv0;
            float v11 = acc[mi][ni][3] + bv1;
            if (FUSE_GELU) {
                v00 = gelu_exact(v00);
                v01 = gelu_exact(v01);
                v10 = gelu_exact(v10);
                v11 = gelu_exact(v11);
            }
            if (HALF_OUT) {
                __half* C = (__half*)Cv;
                *reinterpret_cast<__half2*>(&C[(size_t)r0 * N + col]) =
                    __floats2half2_rn(v00, v01);
                *reinterpret_cast<__half2*>(&C[(size_t)(r0 + 8) * N + col]) =
                    __floats2half2_rn(v10, v11);
            } else {
                float* C = (float*)Cv;
                *reinterpret_cast<float2*>(&C[(size_t)r0 * N + col])       = make_float2(v00, v01);
                *reinterpret_cast<float2*>(&C[(size_t)(r0 + 8) * N + col]) = make_float2(v10, v11);
            }
        }
    }
}

// ---------------- launch ----------------
extern "C" void kernel_launch(void* const* d_in, const int* in_sizes, int n_in,
                              void* d_out, int out_size) {
    const float* x   = (const float*)d_in[0];
    const float* c0a = (const float*)d_in[1];
    const float* c0b = (const float*)d_in[2];
    const float* c0c = (const float*)d_in[3];
    const float* b0  = (const float*)d_in[4];
    const float* c1a = (const float*)d_in[5];
    const float* c1b = (const float*)d_in[6];
    const float* c1c = (const float*)d_in[7];
    const float* b1  = (const float*)d_in[8];
    float* out = (float*)d_out;

    void *pW0, *pW1, *pXh, *pHh;
    cudaGetSymbolAddress(&pW0, g_W0h);
    cudaGetSymbolAddress(&pW1, g_W1h);
    cudaGetSymbolAddress(&pXh, g_Xh);
    cudaGetSymbolAddress(&pHh, g_Hh);
    __half* W0h = (__half*)pW0;
    __half* W1h = (__half*)pW1;
    __half* Xh  = (__half*)pXh;
    __half* Hh  = (__half*)pHh;

    cudaFuncSetAttribute(k_gemm_f16<true, true>,
                         cudaFuncAttributeMaxDynamicSharedMemorySize, GEMM_SMEM);
    cudaFuncSetAttribute(k_gemm_f16<false, false>,
                         cudaFuncAttributeMaxDynamicSharedMemorySize, GEMM_SMEM);

    // 1) convert x -> fp16
    k_x_to_h<<<2048, 1024>>>((const float4*)x, (__half2*)Xh, 8192 * 1024 / 4);
    // 2) materialize transposed TT weight matrices (fp16)
    k_build_w0t<<<4096, 256>>>(c0a, c0b, c0c);
    k_build_w1t<<<1024, 256>>>(c1a, c1b, c1c);
    // 3) Hh = fp16(gelu(Xh @ W0h^T + b0))   [8192 x 4096]
    k_gemm_f16<true, true><<<dim3(4096 / BN, 8192 / BM), 256, GEMM_SMEM>>>(
        Xh, W0h, b0, Hh, 8192, 4096, 1024);
    // 4) out = Hh @ W1h^T + b1              [8192 x 1024] fp32
    k_gemm_f16<false, false><<<dim3(1024 / BN, 8192 / BM), 256, GEMM_SMEM>>>(
        Hh, W1h, b1, out, 8192, 1024, 4096);
}

// round 7
// speedup vs baseline: 1.8953x; 1.2760x over previous
#include <cuda_runtime.h>
#include <cuda_fp16.h>
#include <cstdint>
#include <cstddef>

#define DEV __device__ __forceinline__

// ---------------- scratch (static device allocations: allowed) ----------------
__device__ __half g_W0h[4096u * 1024u];  // 8 MB, W0^T [out=4096][in=1024] fp16
__device__ __half g_W1h[1024u * 4096u];  // 8 MB, W1^T [out=1024][in=4096] fp16
__device__ __half g_Xh [8192u * 1024u];  // 16 MB, fp16 x
__device__ __half g_Hh [8192u * 4096u];  // 64 MB, fp16 gelu(h)

// ---------------- helpers ----------------
DEV uint32_t smem_u32(const void* p) { return (uint32_t)__cvta_generic_to_shared(p); }
DEV void cp_async16(uint32_t dst, const void* src) {
    asm volatile("cp.async.cg.shared.global [%0], [%1], 16;\n" :: "r"(dst), "l"(src));
}
DEV void cp_commit() { asm volatile("cp.async.commit_group;\n" ::: "memory"); }
template <int W> DEV void cp_wait() {
    asm volatile("cp.async.wait_group %0;\n" :: "n"(W) : "memory");
}
DEV void mma_f16(float* c, const uint32_t* a, const uint32_t b0, const uint32_t b1) {
    asm volatile(
        "mma.sync.aligned.m16n8k16.row.col.f32.f16.f16.f32 "
        "{%0,%1,%2,%3}, {%4,%5,%6,%7}, {%8,%9}, {%0,%1,%2,%3};\n"
        : "+f"(c[0]), "+f"(c[1]), "+f"(c[2]), "+f"(c[3])
        : "r"(a[0]), "r"(a[1]), "r"(a[2]), "r"(a[3]), "r"(b0), "r"(b1));
}
DEV void ldsm_x4(uint32_t* r, uint32_t addr) {
    asm volatile("ldmatrix.sync.aligned.m8n8.x4.shared.b16 {%0,%1,%2,%3}, [%4];"
                 : "=r"(r[0]), "=r"(r[1]), "=r"(r[2]), "=r"(r[3]) : "r"(addr));
}
DEV float gelu_exact(float x) { return x * normcdff(x); }

// ---------------- prologue: x (fp32) -> fp16 ----------------
__global__ void k_x_to_h(const float4* __restrict__ x, __half2* __restrict__ xh, int n4) {
    int idx = blockIdx.x * blockDim.x + threadIdx.x;
    if (idx < n4) {
        float4 v = x[idx];
        xh[2 * idx]     = __floats2half2_rn(v.x, v.y);
        xh[2 * idx + 1] = __floats2half2_rn(v.z, v.w);
    }
}

// ---------------- transposed TT weight builders (fp16 out, proven correct) ----
__global__ void k_build_w0t(const float* __restrict__ c0a,
                            const float* __restrict__ c0b,
                            const float* __restrict__ c0c) {
    __shared__ float a_sh[64], c_sh[64], b_sh[1024], bc[1024];
    const int m = blockIdx.x;
    const int o = m >> 8, p = (m >> 4) & 15, q = m & 15;
    const int t = threadIdx.x;

    if (t < 64) {                       // a_sh[i*8+r]
        int i = t >> 3, r = t & 7;
        a_sh[t] = c0a[(i * 16 + o) * 8 + r];
    } else if (t < 128) {               // c_sh[s*8+k]
        int tt = t - 64, s = tt >> 3, k = tt & 7;
        c_sh[tt] = c0c[(s * 8 + k) * 16 + q];
    }
    for (int idx = t; idx < 1024; idx += 256) {   // b_sh[(r*16+j)*8+s]
        int rj = idx >> 3, s = idx & 7;
        b_sh[idx] = c0b[(rj * 16 + p) * 8 + s];
    }
    __syncthreads();
    for (int idx = t; idx < 1024; idx += 256) {   // bc[(r*16+j)*8+k]
        int rj = idx >> 3, k = idx & 7;
        float acc = 0.f;
#pragma unroll
        for (int s = 0; s < 8; s++) acc = fmaf(b_sh[rj * 8 + s], c_sh[s * 8 + k], acc);
        bc[idx] = acc;
    }
    __syncthreads();
    float v[4];
#pragma unroll
    for (int d = 0; d < 4; d++) {
        int n = 4 * t + d;
        int i = n >> 7, j = (n >> 3) & 15, k = n & 7;
        float acc = 0.f;
#pragma unroll
        for (int r = 0; r < 8; r++) acc = fmaf(a_sh[i * 8 + r], bc[(r * 16 + j) * 8 + k], acc);
        v[d] = acc;
    }
    __half2* dst = reinterpret_cast<__half2*>(&g_W0h[(size_t)m * 1024 + 4 * t]);
    dst[0] = __floats2half2_rn(v[0], v[1]);
    dst[1] = __floats2half2_rn(v[2], v[3]);
}

__global__ void k_build_w1t(const float* __restrict__ c1a,
                            const float* __restrict__ c1b,
                            const float* __restrict__ c1c) {
    __shared__ float a_sh[128], c_sh[128], b_sh[1024], bc[2048];
    const int m = blockIdx.x;
    const int o = m >> 7, p = (m >> 3) & 15, q = m & 7;
    const int t = threadIdx.x;

    if (t < 128) {                      // a_sh[i*8+r]
        int i = t >> 3, r = t & 7;
        a_sh[t] = c1a[(i * 8 + o) * 8 + r];
    } else {                            // c_sh[s*16+k]
        int tt = t - 128, s = tt >> 4, k = tt & 15;
        c_sh[tt] = c1c[(s * 16 + k) * 8 + q];
    }
    for (int idx = t; idx < 1024; idx += 256) {   // b_sh[(r*16+j)*8+s]
        int rj = idx >> 3, s = idx & 7;
        b_sh[idx] = c1b[(rj * 16 + p) * 8 + s];
    }
    __syncthreads();
    for (int idx = t; idx < 2048; idx += 256) {   // bc[(r*16+j)*16+k]
        int rj = idx >> 4, k = idx & 15;
        float acc = 0.f;
#pragma unroll
        for (int s = 0; s < 8; s++) acc = fmaf(b_sh[rj * 8 + s], c_sh[s * 16 + k], acc);
        bc[idx] = acc;
    }
    __syncthreads();
    const int i = t >> 4, j = t & 15;   // n = 16t + k
    float v[16];
#pragma unroll
    for (int k = 0; k < 16; k++) {
        float acc = 0.f;
#pragma unroll
        for (int r = 0; r < 8; r++) acc = fmaf(a_sh[i * 8 + r], bc[(r * 16 + j) * 16 + k], acc);
        v[k] = acc;
    }
    __half2* dst = reinterpret_cast<__half2*>(&g_W1h[(size_t)m * 4096 + 16 * t]);
#pragma unroll
    for (int d = 0; d < 8; d++)
        dst[d] = __floats2half2_rn(v[2 * d], v[2 * d + 1]);
}

// ---------------- fp16 GEMM: C = act(A @ B^T + bias) ----------------
// A: [M][K] fp16 row-major; B: [N][K] fp16 row-major (weights pre-transposed).
// BM=BN=128, BK=64 halves, 3-stage cp.async ring, ldmatrix.x4 feed.
// 512 threads = 16 warps in 4(M) x 4(N); warp tile 32x32.
constexpr int BM = 128, BN = 128, BKH = 64, STAGES = 3;
constexpr int STRW = 36;                               // 32 words + 4 pad
constexpr int ROWB = STRW * 4;                         // 144 B row stride
constexpr int A_WORDS = BM * STRW;                     // 4608
constexpr int B_WORDS = BN * STRW;                     // 4608
constexpr int STAGE_WORDS = A_WORDS + B_WORDS;         // 9216
constexpr int STAGE_BYTES = STAGE_WORDS * 4;
constexpr int GEMM_SMEM = STAGES * STAGE_BYTES;        // 110592 B

template <bool FUSE_GELU, bool HALF_OUT>
__global__ void __launch_bounds__(512, 2)
k_gemm_f16(const __half* __restrict__ A, const __half* __restrict__ Bg,
           const float* __restrict__ bias, void* __restrict__ Cv,
           int M, int N, int K) {
    extern __shared__ uint32_t smem_w[];
    const uint32_t sbase = smem_u32(smem_w);

    const int tid = threadIdx.x;
    const int m0 = blockIdx.y * BM;
    const int n0 = blockIdx.x * BN;
    const int lane = tid & 31;
    const int warp = tid >> 5;
    const int g = lane >> 2, tig = lane & 3;
    const int wm = (warp & 3) * 32;        // 4 warps in M
    const int wn = (warp >> 2) * 32;       // 4 warps in N

    const int T = K / BKH;

    // cp.async mapping: 512 threads, 2 chunks A + 2 chunks B each
    // row = tid>>2 (0..127); word base = (tid&3)*8; chunks at +0 and +4 words
    const int crow = tid >> 2;
    const int cw = (tid & 3) * 8;
    const __half* agl = A + (size_t)(m0 + crow) * K + cw * 2;
    const __half* bgl = Bg + (size_t)(n0 + crow) * K + cw * 2;
    const uint32_t sa_off = (uint32_t)(crow * STRW + cw) * 4u;

    auto issue = [&](int t) {
        const int st = t % STAGES;
        const uint32_t sa = sbase + (uint32_t)(st * STAGE_BYTES) + sa_off;
        const uint32_t sb = sa + (uint32_t)A_WORDS * 4u;
        const size_t koff = (size_t)t * BKH;
        cp_async16(sa,       agl + koff);
        cp_async16(sa + 16u, agl + koff + 8);
        cp_async16(sb,       bgl + koff);
        cp_async16(sb + 16u, bgl + koff + 8);
        cp_commit();
    };

    // ldmatrix base addresses (stage 0)
    // A m16k16 frag: th0-15 -> rows wm+mi*16+(lane&15) @k0; th16-31 same rows @k8
    const uint32_t aLdsm = sbase
        + (uint32_t)((wm + (lane & 15)) * ROWB)
        + (uint32_t)((lane >> 4) * 16);
    // B frag pair (two n8k16 per LDSM.x4)
    const uint32_t bLdsm = sbase + (uint32_t)A_WORDS * 4u
        + (uint32_t)((wn + ((lane >> 4) << 3) + (lane & 7)) * ROWB)
        + (uint32_t)(((lane >> 3) & 1) * 16);

    float acc[2][4][4];
#pragma unroll
    for (int mi = 0; mi < 2; mi++)
#pragma unroll
        for (int ni = 0; ni < 4; ni++)
#pragma unroll
            for (int q = 0; q < 4; q++) acc[mi][ni][q] = 0.f;

    issue(0);
    issue(1);

    for (int t = 0; t < T; ++t) {
        cp_wait<1>();            // stage t landed
        __syncthreads();         // everyone done with buffer (t+2)%3
        if (t + 2 < T) issue(t + 2);

        const uint32_t stoff = (uint32_t)((t % STAGES) * STAGE_BYTES);
#pragma unroll
        for (int k16 = 0; k16 < 4; ++k16) {          // 4 x K=16 per stage
            const uint32_t kb = (uint32_t)(k16 * 32); // 8 words = 32 B
            uint32_t af[2][4];
#pragma unroll
            for (int mi = 0; mi < 2; ++mi)
                ldsm_x4(af[mi], aLdsm + stoff + (uint32_t)(mi * 16 * ROWB) + kb);
            uint32_t bq[2][4];
#pragma unroll
            for (int nip = 0; nip < 2; ++nip)
                ldsm_x4(bq[nip], bLdsm + stoff + (uint32_t)(nip * 16 * ROWB) + kb);
#pragma unroll
            for (int mi = 0; mi < 2; ++mi)
#pragma unroll
                for (int ni = 0; ni < 4; ++ni)
                    mma_f16(acc[mi][ni], af[mi], bq[ni >> 1][2 * (ni & 1)],
                            bq[ni >> 1][2 * (ni & 1) + 1]);
        }
    }

    // ---- epilogue ----
#pragma unroll
    for (int mi = 0; mi < 2; ++mi) {
        const int r0 = m0 + wm + mi * 16 + g;
#pragma unroll
        for (int ni = 0; ni < 4; ++ni) {
            const int col = n0 + wn + ni * 8 + tig * 2;
            const float bv0 = bias[col], bv1 = bias[col + 1];
            float v00 = acc[mi][ni][0] + bv0;
            float v01 = acc[mi][ni][1] + bv1;
            float v10 = acc[mi][ni][2] + bv0;
            float v11 = acc[mi][ni][3] + bv1;
            if (FUSE_GELU) {
                v00 = gelu_exact(v00);
                v01 = gelu_exact(v01);
                v10 = gelu_exact(v10);
                v11 = gelu_exact(v11);
            }
            if (HALF_OUT) {
                __half* C = (__half*)Cv;
                *reinterpret_cast<__half2*>(&C[(size_t)r0 * N + col]) =
                    __floats2half2_rn(v00, v01);
                *reinterpret_cast<__half2*>(&C[(size_t)(r0 + 8) * N + col]) =
                    __floats2half2_rn(v10, v11);
            } else {
                float* C = (float*)Cv;
                *reinterpret_cast<float2*>(&C[(size_t)r0 * N + col])       = make_float2(v00, v01);
                *reinterpret_cast<float2*>(&C[(size_t)(r0 + 8) * N + col]) = make_float2(v10, v11);
            }
        }
    }
}

// ---------------- launch ----------------
extern "C" void kernel_launch(void* const* d_in, const int* in_sizes, int n_in,
                              void* d_out, int out_size) {
    const float* x   = (const float*)d_in[0];
    const float* c0a = (const float*)d_in[1];
    const float* c0b = (const float*)d_in[2];
    const float* c0c = (const float*)d_in[3];
    const float* b0  = (const float*)d_in[4];
    const float* c1a = (const float*)d_in[5];
    const float* c1b = (const float*)d_in[6];
    const float* c1c = (const float*)d_in[7];
    const float* b1  = (const float*)d_in[8];
    float* out = (float*)d_out;

    void *pW0, *pW1, *pXh, *pHh;
    cudaGetSymbolAddress(&pW0, g_W0h);
    cudaGetSymbolAddress(&pW1, g_W1h);
    cudaGetSymbolAddress(&pXh, g_Xh);
    cudaGetSymbolAddress(&pHh, g_Hh);
    __half* W0h = (__half*)pW0;
    __half* W1h = (__half*)pW1;
    __half* Xh  = (__half*)pXh;
    __half* Hh  = (__half*)pHh;

    cudaFuncSetAttribute(k_gemm_f16<true, true>,
                         cudaFuncAttributeMaxDynamicSharedMemorySize, GEMM_SMEM);
    cudaFuncSetAttribute(k_gemm_f16<false, false>,
                         cudaFuncAttributeMaxDynamicSharedMemorySize, GEMM_SMEM);

    // 1) convert x -> fp16
    k_x_to_h<<<2048, 1024>>>((const float4*)x, (__half2*)Xh, 8192 * 1024 / 4);
    // 2) materialize transposed TT weight matrices (fp16)
    k_build_w0t<<<4096, 256>>>(c0a, c0b, c0c);
    k_build_w1t<<<1024, 256>>>(c1a, c1b, c1c);
    // 3) Hh = fp16(gelu(Xh @ W0h^T + b0))   [8192 x 4096]
    k_gemm_f16<true, true><<<dim3(4096 / BN, 8192 / BM), 512, GEMM_SMEM>>>(
        Xh, W0h, b0, Hh, 8192, 4096, 1024);
    // 4) out = Hh @ W1h^T + b1              [8192 x 1024] fp32
    k_gemm_f16<false, false><<<dim3(1024 / BN, 8192 / BM), 512, GEMM_SMEM>>>(
        Hh, W1h, b1, out, 8192, 1024, 4096);
}

// round 8
// speedup vs baseline: 1.8970x; 1.0009x over previous
#include <cuda_runtime.h>
#include <cuda_fp16.h>
#include <cstdint>
#include <cstddef>

#define DEV __device__ __forceinline__

// ---------------- scratch (static device allocations: allowed) ----------------
__device__ __half g_W0h[4096u * 1024u];  // 8 MB, W0^T [out=4096][in=1024] fp16
__device__ __half g_W1h[1024u * 4096u];  // 8 MB, W1^T [out=1024][in=4096] fp16
__device__ __half g_Xh [8192u * 1024u];  // 16 MB, fp16 x
__device__ __half g_Hh [8192u * 4096u];  // 64 MB, fp16 gelu(h)

// ---------------- helpers ----------------
DEV uint32_t smem_u32(const void* p) { return (uint32_t)__cvta_generic_to_shared(p); }
DEV void cp_async16(uint32_t dst, const void* src) {
    asm volatile("cp.async.cg.shared.global [%0], [%1], 16;\n" :: "r"(dst), "l"(src));
}
DEV void cp_commit() { asm volatile("cp.async.commit_group;\n" ::: "memory"); }
template <int W> DEV void cp_wait() {
    asm volatile("cp.async.wait_group %0;\n" :: "n"(W) : "memory");
}
DEV void mma_f16(float* c, const uint32_t* a, const uint32_t b0, const uint32_t b1) {
    asm volatile(
        "mma.sync.aligned.m16n8k16.row.col.f32.f16.f16.f32 "
        "{%0,%1,%2,%3}, {%4,%5,%6,%7}, {%8,%9}, {%0,%1,%2,%3};\n"
        : "+f"(c[0]), "+f"(c[1]), "+f"(c[2]), "+f"(c[3])
        : "r"(a[0]), "r"(a[1]), "r"(a[2]), "r"(a[3]), "r"(b0), "r"(b1));
}
DEV void ldsm_x4(uint32_t* r, uint32_t addr) {
    asm volatile("ldmatrix.sync.aligned.m8n8.x4.shared.b16 {%0,%1,%2,%3}, [%4];"
                 : "=r"(r[0]), "=r"(r[1]), "=r"(r[2]), "=r"(r[3]) : "r"(addr));
}
// exact-erf gelu via the cheap erff polynomial path (same accuracy as normcdff)
DEV float gelu_exact(float x) {
    return 0.5f * x * (1.0f + erff(x * 0.70710678118654752f));
}

// ---------------- prologue: x (fp32) -> fp16 ----------------
__global__ void k_x_to_h(const float4* __restrict__ x, __half2* __restrict__ xh, int n4) {
    int idx = blockIdx.x * blockDim.x + threadIdx.x;
    if (idx < n4) {
        float4 v = x[idx];
        xh[2 * idx]     = __floats2half2_rn(v.x, v.y);
        xh[2 * idx + 1] = __floats2half2_rn(v.z, v.w);
    }
}

// ---------------- transposed TT weight builders (fp16 out, proven correct) ----
__global__ void k_build_w0t(const float* __restrict__ c0a,
                            const float* __restrict__ c0b,
                            const float* __restrict__ c0c) {
    __shared__ float a_sh[64], c_sh[64], b_sh[1024], bc[1024];
    const int m = blockIdx.x;
    const int o = m >> 8, p = (m >> 4) & 15, q = m & 15;
    const int t = threadIdx.x;

    if (t < 64) {                       // a_sh[i*8+r]
        int i = t >> 3, r = t & 7;
        a_sh[t] = c0a[(i * 16 + o) * 8 + r];
    } else if (t < 128) {               // c_sh[s*8+k]
        int tt = t - 64, s = tt >> 3, k = tt & 7;
        c_sh[tt] = c0c[(s * 8 + k) * 16 + q];
    }
    for (int idx = t; idx < 1024; idx += 256) {   // b_sh[(r*16+j)*8+s]
        int rj = idx >> 3, s = idx & 7;
        b_sh[idx] = c0b[(rj * 16 + p) * 8 + s];
    }
    __syncthreads();
    for (int idx = t; idx < 1024; idx += 256) {   // bc[(r*16+j)*8+k]
        int rj = idx >> 3, k = idx & 7;
        float acc = 0.f;
#pragma unroll
        for (int s = 0; s < 8; s++) acc = fmaf(b_sh[rj * 8 + s], c_sh[s * 8 + k], acc);
        bc[idx] = acc;
    }
    __syncthreads();
    float v[4];
#pragma unroll
    for (int d = 0; d < 4; d++) {
        int n = 4 * t + d;
        int i = n >> 7, j = (n >> 3) & 15, k = n & 7;
        float acc = 0.f;
#pragma unroll
        for (int r = 0; r < 8; r++) acc = fmaf(a_sh[i * 8 + r], bc[(r * 16 + j) * 8 + k], acc);
        v[d] = acc;
    }
    __half2* dst = reinterpret_cast<__half2*>(&g_W0h[(size_t)m * 1024 + 4 * t]);
    dst[0] = __floats2half2_rn(v[0], v[1]);
    dst[1] = __floats2half2_rn(v[2], v[3]);
}

__global__ void k_build_w1t(const float* __restrict__ c1a,
                            const float* __restrict__ c1b,
                            const float* __restrict__ c1c) {
    __shared__ float a_sh[128], c_sh[128], b_sh[1024], bc[2048];
    const int m = blockIdx.x;
    const int o = m >> 7, p = (m >> 3) & 15, q = m & 7;
    const int t = threadIdx.x;

    if (t < 128) {                      // a_sh[i*8+r]
        int i = t >> 3, r = t & 7;
        a_sh[t] = c1a[(i * 8 + o) * 8 + r];
    } else {                            // c_sh[s*16+k]
        int tt = t - 128, s = tt >> 4, k = tt & 15;
        c_sh[tt] = c1c[(s * 16 + k) * 8 + q];
    }
    for (int idx = t; idx < 1024; idx += 256) {   // b_sh[(r*16+j)*8+s]
        int rj = idx >> 3, s = idx & 7;
        b_sh[idx] = c1b[(rj * 16 + p) * 8 + s];
    }
    __syncthreads();
    for (int idx = t; idx < 2048; idx += 256) {   // bc[(r*16+j)*16+k]
        int rj = idx >> 4, k = idx & 15;
        float acc = 0.f;
#pragma unroll
        for (int s = 0; s < 8; s++) acc = fmaf(b_sh[rj * 8 + s], c_sh[s * 16 + k], acc);
        bc[idx] = acc;
    }
    __syncthreads();
    const int i = t >> 4, j = t & 15;   // n = 16t + k
    float v[16];
#pragma unroll
    for (int k = 0; k < 16; k++) {
        float acc = 0.f;
#pragma unroll
        for (int r = 0; r < 8; r++) acc = fmaf(a_sh[i * 8 + r], bc[(r * 16 + j) * 16 + k], acc);
        v[k] = acc;
    }
    __half2* dst = reinterpret_cast<__half2*>(&g_W1h[(size_t)m * 4096 + 16 * t]);
#pragma unroll
    for (int d = 0; d < 8; d++)
        dst[d] = __floats2half2_rn(v[2 * d], v[2 * d + 1]);
}

// ---------------- fp16 GEMM: C = act(A @ B^T + bias) ----------------
// A: [M][K] fp16 row-major; B: [N][K] fp16 row-major (weights pre-transposed).
// BM=BN=128, BK=64 halves, 3-stage cp.async ring, ldmatrix.x4 feed.
// 512 threads = 16 warps in 4(M) x 4(N); warp tile 32x32.
constexpr int BM = 128, BN = 128, BKH = 64, STAGES = 3;
constexpr int STRW = 36;                               // 32 words + 4 pad
constexpr int ROWB = STRW * 4;                         // 144 B row stride
constexpr int A_WORDS = BM * STRW;                     // 4608
constexpr int B_WORDS = BN * STRW;                     // 4608
constexpr int STAGE_WORDS = A_WORDS + B_WORDS;         // 9216
constexpr int STAGE_BYTES = STAGE_WORDS * 4;
constexpr uint32_t STAGE_LAST = 2u * STAGE_BYTES;
constexpr int GEMM_SMEM = STAGES * STAGE_BYTES;        // 110592 B

template <bool FUSE_GELU, bool HALF_OUT>
__global__ void __launch_bounds__(512, 2)
k_gemm_f16(const __half* __restrict__ A, const __half* __restrict__ Bg,
           const float* __restrict__ bias, void* __restrict__ Cv,
           int M, int N, int K) {
    extern __shared__ uint32_t smem_w[];
    const uint32_t sbase = smem_u32(smem_w);

    const int tid = threadIdx.x;
    const int m0 = blockIdx.y * BM;
    const int n0 = blockIdx.x * BN;
    const int lane = tid & 31;
    const int warp = tid >> 5;
    const int g = lane >> 2, tig = lane & 3;
    const int wm = (warp & 3) * 32;        // 4 warps in M
    const int wn = (warp >> 2) * 32;       // 4 warps in N

    const int T = K / BKH;

    // cp.async mapping: 512 threads, 2 chunks A + 2 chunks B each
    const int crow = tid >> 2;
    const int cw = (tid & 3) * 8;
    const __half* aNext = A + (size_t)(m0 + crow) * K + cw * 2;
    const __half* bNext = Bg + (size_t)(n0 + crow) * K + cw * 2;
    const uint32_t sa_off = (uint32_t)(crow * STRW + cw) * 4u;

    // issue one stage at smem offset `stoff`, then advance global pointers
    auto issue_at = [&](uint32_t stoff) {
        const uint32_t sa = sbase + stoff + sa_off;
        const uint32_t sb = sa + (uint32_t)A_WORDS * 4u;
        cp_async16(sa,       aNext);
        cp_async16(sa + 16u, aNext + 8);
        cp_async16(sb,       bNext);
        cp_async16(sb + 16u, bNext + 8);
        cp_commit();
        aNext += BKH;
        bNext += BKH;
    };

    // ldmatrix base addresses (stage 0)
    const uint32_t aLdsm = sbase
        + (uint32_t)((wm + (lane & 15)) * ROWB)
        + (uint32_t)((lane >> 4) * 16);
    const uint32_t bLdsm = sbase + (uint32_t)A_WORDS * 4u
        + (uint32_t)((wn + ((lane >> 4) << 3) + (lane & 7)) * ROWB)
        + (uint32_t)(((lane >> 3) & 1) * 16);

    float acc[2][4][4];
#pragma unroll
    for (int mi = 0; mi < 2; mi++)
#pragma unroll
        for (int ni = 0; ni < 4; ni++)
#pragma unroll
            for (int q = 0; q < 4; q++) acc[mi][ni][q] = 0.f;

    issue_at(0);
    issue_at(STAGE_BYTES);

    uint32_t stoff_i = STAGE_LAST;    // smem offset for next issue (stage t+2)
    uint32_t stoff_c = 0;             // smem offset for current compute (stage t)

    for (int t = 0; t < T; ++t) {
        cp_wait<1>();            // stage t landed
        __syncthreads();         // everyone done with the buffer about to be refilled
        if (t + 2 < T) issue_at(stoff_i);
        stoff_i = (stoff_i == STAGE_LAST) ? 0u : stoff_i + (uint32_t)STAGE_BYTES;

        const uint32_t aS = aLdsm + stoff_c;
        const uint32_t bS = bLdsm + stoff_c;
        stoff_c = (stoff_c == STAGE_LAST) ? 0u : stoff_c + (uint32_t)STAGE_BYTES;
#pragma unroll
        for (int k16 = 0; k16 < 4; ++k16) {          // 4 x K=16 per stage
            const uint32_t kb = (uint32_t)(k16 * 32); // 8 words = 32 B
            uint32_t bq[2][4];
            ldsm_x4(bq[0], bS + kb);                  // B first: feeds all 8 MMAs
            ldsm_x4(bq[1], bS + (uint32_t)(16 * ROWB) + kb);
            uint32_t af[2][4];
            ldsm_x4(af[0], aS + kb);
            ldsm_x4(af[1], aS + (uint32_t)(16 * ROWB) + kb);
#pragma unroll
            for (int mi = 0; mi < 2; ++mi)
#pragma unroll
                for (int ni = 0; ni < 4; ++ni)
                    mma_f16(acc[mi][ni], af[mi], bq[ni >> 1][2 * (ni & 1)],
                            bq[ni >> 1][2 * (ni & 1) + 1]);
        }
    }

    // ---- epilogue ----
#pragma unroll
    for (int mi = 0; mi < 2; ++mi) {
        const int r0 = m0 + wm + mi * 16 + g;
#pragma unroll
        for (int ni = 0; ni < 4; ++ni) {
            const int col = n0 + wn + ni * 8 + tig * 2;
            const float bv0 = bias[col], bv1 = bias[col + 1];
            float v00 = acc[mi][ni][0] + bv0;
            float v01 = acc[mi][ni][1] + bv1;
            float v10 = acc[mi][ni][2] + bv0;
            float v11 = acc[mi][ni][3] + bv1;
            if (FUSE_GELU) {
                v00 = gelu_exact(v00);
                v01 = gelu_exact(v01);
                v10 = gelu_exact(v10);
                v11 = gelu_exact(v11);
            }
            if (HALF_OUT) {
                __half* C = (__half*)Cv;
                *reinterpret_cast<__half2*>(&C[(size_t)r0 * N + col]) =
                    __floats2half2_rn(v00, v01);
                *reinterpret_cast<__half2*>(&C[(size_t)(r0 + 8) * N + col]) =
                    __floats2half2_rn(v10, v11);
            } else {
                float* C = (float*)Cv;
                *reinterpret_cast<float2*>(&C[(size_t)r0 * N + col])       = make_float2(v00, v01);
                *reinterpret_cast<float2*>(&C[(size_t)(r0 + 8) * N + col]) = make_float2(v10, v11);
            }
        }
    }
}

// ---------------- launch ----------------
extern "C" void kernel_launch(void* const* d_in, const int* in_sizes, int n_in,
                              void* d_out, int out_size) {
    const float* x   = (const float*)d_in[0];
    const float* c0a = (const float*)d_in[1];
    const float* c0b = (const float*)d_in[2];
    const float* c0c = (const float*)d_in[3];
    const float* b0  = (const float*)d_in[4];
    const float* c1a = (const float*)d_in[5];
    const float* c1b = (const float*)d_in[6];
    const float* c1c = (const float*)d_in[7];
    const float* b1  = (const float*)d_in[8];
    float* out = (float*)d_out;

    void *pW0, *pW1, *pXh, *pHh;
    cudaGetSymbolAddress(&pW0, g_W0h);
    cudaGetSymbolAddress(&pW1, g_W1h);
    cudaGetSymbolAddress(&pXh, g_Xh);
    cudaGetSymbolAddress(&pHh, g_Hh);
    __half* W0h = (__half*)pW0;
    __half* W1h = (__half*)pW1;
    __half* Xh  = (__half*)pXh;
    __half* Hh  = (__half*)pHh;

    cudaFuncSetAttribute(k_gemm_f16<true, true>,
                         cudaFuncAttributeMaxDynamicSharedMemorySize, GEMM_SMEM);
    cudaFuncSetAttribute(k_gemm_f16<false, false>,
                         cudaFuncAttributeMaxDynamicSharedMemorySize, GEMM_SMEM);

    // 1) convert x -> fp16
    k_x_to_h<<<2048, 1024>>>((const float4*)x, (__half2*)Xh, 8192 * 1024 / 4);
    // 2) materialize transposed TT weight matrices (fp16)
    k_build_w0t<<<4096, 256>>>(c0a, c0b, c0c);
    k_build_w1t<<<1024, 256>>>(c1a, c1b, c1c);
    // 3) Hh = fp16(gelu(Xh @ W0h^T + b0))   [8192 x 4096]
    k_gemm_f16<true, true><<<dim3(4096 / BN, 8192 / BM), 512, GEMM_SMEM>>>(
        Xh, W0h, b0, Hh, 8192, 4096, 1024);
    // 4) out = Hh @ W1h^T + b1              [8192 x 1024] fp32
    k_gemm_f16<false, false><<<dim3(1024 / BN, 8192 / BM), 512, GEMM_SMEM>>>(
        Hh, W1h, b1, out, 8192, 1024, 4096);
}